// round 1
// baseline (speedup 1.0000x reference)
#include <cuda_runtime.h>

#define NN 100000
#define EE 3200000
#define GG 100
#define FI 16
#define HH 48
#define KK 5

// ---------------- device scratch (no allocs allowed) ----------------
__device__ float g_B[NN * HH];
__device__ float g_C[NN * HH];
__device__ float g_D[NN * HH];
__device__ float g_H[NN * HH];
__device__ float g_OUT[NN * HH];
__device__ float g_dis[NN];
__device__ float g_diag[NN];
__device__ int   g_outc[NN];
__device__ int   g_inc[NN];
__device__ int   g_fill[NN];
__device__ int   g_rowptr[NN + 1];
__device__ int   g_csrc[EE];
__device__ float g_cw[EE];
__device__ float g_pool[GG * HH];

// ---------------- CSR build ----------------
__global__ void deg_k(const int* __restrict__ ei) {
    int e = blockIdx.x * blockDim.x + threadIdx.x;
    if (e >= EE) return;
    atomicAdd(&g_outc[ei[e]], 1);       // out-degree (by src)
    atomicAdd(&g_inc[ei[EE + e]], 1);   // in-degree  (by dst) for CSR
}

// single-block exclusive scan of g_inc -> g_rowptr (N=100000, 1024 threads, 98/thread)
__global__ void scan_k() {
    __shared__ int ssum[1024];
    const int t = threadIdx.x;
    const int chunk = 98;
    int start = t * chunk;
    int end = start + chunk; if (end > NN) end = NN;
    int s = 0;
    for (int i = start; i < end; ++i) s += g_inc[i];
    ssum[t] = s;
    __syncthreads();
    // Hillis-Steele inclusive scan
    for (int off = 1; off < 1024; off <<= 1) {
        int v = (t >= off) ? ssum[t - off] : 0;
        __syncthreads();
        ssum[t] += v;
        __syncthreads();
    }
    int run = (t == 0) ? 0 : ssum[t - 1];
    for (int i = start; i < end; ++i) { g_rowptr[i] = run; run += g_inc[i]; }
    if (t == 1023) g_rowptr[NN] = run;  // == EE
}

__global__ void nodeinit_k(const int* __restrict__ batch, const float* __restrict__ lmax) {
    int n = blockIdx.x * blockDim.x + threadIdx.x;
    if (n >= NN) return;
    int dg = g_outc[n];
    g_dis[n]  = (dg > 0) ? rsqrtf((float)dg) : 0.f;
    g_diag[n] = 2.f / lmax[batch[n]] - 1.f;
}

__global__ void wedge_k(const int* __restrict__ ei, const int* __restrict__ batch,
                        const float* __restrict__ lmax) {
    int e = blockIdx.x * blockDim.x + threadIdx.x;
    if (e >= EE) return;
    int s = ei[e];
    int d = ei[EE + e];
    float w = -2.f * g_dis[s] * g_dis[d] / lmax[batch[s]];
    int pos = g_rowptr[d] + atomicAdd(&g_fill[d], 1);
    g_csrc[pos] = s;
    g_cw[pos]   = w;
}

// ---------------- propagation: P = alpha*(L_hat @ T) - beta*Tprev ----------------
// gather form over in-edges (CSR by dst). C = F/4 float4 chunks per node row.
template <int C>
__global__ void prop_k(const float4* __restrict__ T, const float4* __restrict__ Tp,
                       float4* __restrict__ P, float alpha, int useprev) {
    int t = blockIdx.x * blockDim.x + threadIdx.x;
    if (t >= NN * C) return;
    int n = t / C;
    int c = t - n * C;
    float d = g_diag[n];
    float4 v = T[t];
    float4 acc = make_float4(d * v.x, d * v.y, d * v.z, d * v.w);
    int e1 = g_rowptr[n + 1];
    for (int j = g_rowptr[n]; j < e1; ++j) {
        int   s = __ldg(&g_csrc[j]);
        float w = __ldg(&g_cw[j]);
        float4 u = __ldg(&T[s * C + c]);
        acc.x += w * u.x; acc.y += w * u.y; acc.z += w * u.z; acc.w += w * u.w;
    }
    float4 r;
    if (useprev) {
        float4 p = Tp[t];
        r = make_float4(alpha * acc.x - p.x, alpha * acc.y - p.y,
                        alpha * acc.z - p.z, alpha * acc.w - p.w);
    } else {
        r = acc;
    }
    P[t] = r;
}

// ---------------- GEMM: OUT (+)= T[N,F] @ W[F,48]; optional relu(+bias) -> Hout ----------------
template <int F>
__global__ void gemm_k(const float* __restrict__ T, const float* __restrict__ W,
                       const float* __restrict__ bias, float* __restrict__ OUT,
                       float* __restrict__ Hout, int accum) {
    __shared__ float Ws[F * 48];
    __shared__ float Ts[32 * F];
    const int tid = threadIdx.y * 48 + threadIdx.x;
    const int n0 = blockIdx.x * 32;
    for (int i = tid; i < F * 48; i += 384) Ws[i] = W[i];
    for (int i = tid; i < 32 * F; i += 384) Ts[i] = T[n0 * F + i];
    __syncthreads();
    const int h = threadIdx.x;
    const int y = threadIdx.y;
    float a0 = 0.f, a1 = 0.f, a2 = 0.f, a3 = 0.f;
#pragma unroll
    for (int f = 0; f < F; ++f) {
        float w = Ws[f * 48 + h];
        a0 += Ts[(y     ) * F + f] * w;
        a1 += Ts[(y +  8) * F + f] * w;
        a2 += Ts[(y + 16) * F + f] * w;
        a3 += Ts[(y + 24) * F + f] * w;
    }
    float accs[4] = {a0, a1, a2, a3};
#pragma unroll
    for (int q = 0; q < 4; ++q) {
        int idx = (n0 + y + q * 8) * 48 + h;
        float o = accs[q];
        if (accum) o += OUT[idx];
        if (Hout) Hout[idx] = fmaxf(o + bias[h], 0.f);
        else      OUT[idx] = o;
    }
}

// ---------------- pooling: pooled[g,h] = sum over 1000 contiguous nodes ----------------
__global__ void pool_k(const float* __restrict__ Hin) {
    __shared__ float red[8][48];
    const int g = blockIdx.x;
    const int h = threadIdx.x;
    const int y = threadIdx.y;
    const float* base = Hin + (size_t)g * 1000 * 48;
    float s = 0.f;
    for (int i = y; i < 1000; i += 8) s += base[i * 48 + h];
    red[y][h] = s;
    __syncthreads();
    if (y == 0) {
        float t = 0.f;
#pragma unroll
        for (int q = 0; q < 8; ++q) t += red[q][h];
        g_pool[g * 48 + h] = t;
    }
}

// ---------------- MLP head: relu(pooled@fc1+b1)@fc2+b2 ----------------
__global__ void mlp_k(const float* __restrict__ fc1w, const float* __restrict__ fc1b,
                      const float* __restrict__ fc2w, const float* __restrict__ fc2b,
                      float* __restrict__ out) {
    const int g = blockIdx.x;
    const int j = threadIdx.x;  // 0..31
    float a = fc1b[j];
#pragma unroll
    for (int f = 0; f < 48; ++f) a += g_pool[g * 48 + f] * fc1w[f * 32 + j];
    a = fmaxf(a, 0.f);
    float v = a * fc2w[j];
#pragma unroll
    for (int off = 16; off; off >>= 1) v += __shfl_down_sync(0xffffffffu, v, off);
    if (j == 0) out[g] = v + fc2b[0];
}

// ---------------- one ChebConv layer driver ----------------
template <int F>
static void run_layer(const float* IN, const float* W, const float* b,
                      float* Bb, float* Cb, float* Db, float* OUTb, float* Hout) {
    const int C4 = F / 4;
    const int pb = (NN * C4 + 191) / 192;
    dim3 gb(48, 8);
    const int NGB = NN / 32;  // 3125

    // k=0: OUT = IN @ W0
    gemm_k<F><<<NGB, gb>>>(IN, W, b, OUTb, nullptr, 0);
    // T1 = L_hat @ IN
    prop_k<C4><<<pb, 192>>>((const float4*)IN, nullptr, (float4*)Bb, 1.f, 0);
    gemm_k<F><<<NGB, gb>>>(Bb, W + 1 * F * 48, b, OUTb, nullptr, 1);
    // T2 = 2*L_hat@T1 - T0
    prop_k<C4><<<pb, 192>>>((const float4*)Bb, (const float4*)IN, (float4*)Cb, 2.f, 1);
    gemm_k<F><<<NGB, gb>>>(Cb, W + 2 * F * 48, b, OUTb, nullptr, 1);
    // T3
    prop_k<C4><<<pb, 192>>>((const float4*)Cb, (const float4*)Bb, (float4*)Db, 2.f, 1);
    gemm_k<F><<<NGB, gb>>>(Db, W + 3 * F * 48, b, OUTb, nullptr, 1);
    // T4 (overwrite Bb; its old contents no longer needed)
    prop_k<C4><<<pb, 192>>>((const float4*)Db, (const float4*)Cb, (float4*)Bb, 2.f, 1);
    // final accumulate + bias + relu -> Hout
    gemm_k<F><<<NGB, gb>>>(Bb, W + 4 * F * 48, b, OUTb, Hout, 1);
}

extern "C" void kernel_launch(void* const* d_in, const int* in_sizes, int n_in,
                              void* d_out, int out_size) {
    (void)in_sizes; (void)n_in; (void)out_size;
    const float* x     = (const float*)d_in[0];
    const int*   ei    = (const int*)  d_in[1];
    const int*   batch = (const int*)  d_in[2];
    const float* lmax  = (const float*)d_in[3];
    const float* W1 = (const float*)d_in[4];  const float* b1 = (const float*)d_in[5];
    const float* W2 = (const float*)d_in[6];  const float* b2 = (const float*)d_in[7];
    const float* W3 = (const float*)d_in[8];  const float* b3 = (const float*)d_in[9];
    const float* W4 = (const float*)d_in[10]; const float* b4 = (const float*)d_in[11];
    const float* W5 = (const float*)d_in[12]; const float* b5 = (const float*)d_in[13];
    const float* fc1w = (const float*)d_in[14]; const float* fc1b = (const float*)d_in[15];
    const float* fc2w = (const float*)d_in[16]; const float* fc2b = (const float*)d_in[17];
    float* out = (float*)d_out;

    void* p;
    cudaGetSymbolAddress(&p, g_B);    float* Bb   = (float*)p;
    cudaGetSymbolAddress(&p, g_C);    float* Cb   = (float*)p;
    cudaGetSymbolAddress(&p, g_D);    float* Db   = (float*)p;
    cudaGetSymbolAddress(&p, g_H);    float* Hb   = (float*)p;
    cudaGetSymbolAddress(&p, g_OUT);  float* OUTb = (float*)p;
    cudaGetSymbolAddress(&p, g_outc); void* outc_p = p;
    cudaGetSymbolAddress(&p, g_inc);  void* inc_p  = p;
    cudaGetSymbolAddress(&p, g_fill); void* fill_p = p;

    cudaMemsetAsync(outc_p, 0, NN * sizeof(int));
    cudaMemsetAsync(inc_p,  0, NN * sizeof(int));
    cudaMemsetAsync(fill_p, 0, NN * sizeof(int));

    const int EB = (EE + 255) / 256;
    deg_k<<<EB, 256>>>(ei);
    scan_k<<<1, 1024>>>();
    nodeinit_k<<<(NN + 255) / 256, 256>>>(batch, lmax);
    wedge_k<<<EB, 256>>>(ei, batch, lmax);

    run_layer<FI>(x,  W1, b1, Bb, Cb, Db, OUTb, Hb);
    run_layer<HH>(Hb, W2, b2, Bb, Cb, Db, OUTb, Hb);
    run_layer<HH>(Hb, W3, b3, Bb, Cb, Db, OUTb, Hb);
    run_layer<HH>(Hb, W4, b4, Bb, Cb, Db, OUTb, Hb);
    run_layer<HH>(Hb, W5, b5, Bb, Cb, Db, OUTb, Hb);

    pool_k<<<GG, dim3(48, 8)>>>(Hb);
    mlp_k<<<GG, 32>>>(fc1w, fc1b, fc2w, fc2b, out);
}